// round 2
// baseline (speedup 1.0000x reference)
#include <cuda_runtime.h>
#include <math.h>

// Problem dims (fixed by reference)
#define BB 8
#define TT 2048
#define DD 1024
#define HD 64
#define MM 64
#define SSZ (TT + MM)          // 2112 keys/values per batch
#define BT (BB * TT)           // 16384 query rows total

// Scratch (allocation-free rule: __device__ globals)
__device__ float g_q[BT * HD];          // prescaled by d^-0.5
__device__ float g_k[BB * SSZ * HD];
__device__ float g_v[BB * SSZ * HD];

// ---------------------------------------------------------------------------
// Kernel 1: layernorm(c_emb) -> broadcast into tail of g_k / g_v for all b
// ---------------------------------------------------------------------------
__global__ void ln_kernel(const float* __restrict__ c_emb,
                          const float* __restrict__ gamma,
                          const float* __restrict__ beta) {
    int m = blockIdx.x;        // memory token
    int t = threadIdx.x;       // feature 0..63
    __shared__ float red[64];

    float v = c_emb[m * HD + t];
    red[t] = v;
    __syncthreads();
    for (int off = 32; off > 0; off >>= 1) {
        if (t < off) red[t] += red[t + off];
        __syncthreads();
    }
    float mu = red[0] * (1.0f / HD);
    __syncthreads();
    float dv = v - mu;
    red[t] = dv * dv;
    __syncthreads();
    for (int off = 32; off > 0; off >>= 1) {
        if (t < off) red[t] += red[t + off];
        __syncthreads();
    }
    float var = red[0] * (1.0f / HD);
    float y = dv * rsqrtf(var + 1e-5f) * gamma[t] + beta[t];

    #pragma unroll
    for (int b = 0; b < BB; b++) {
        int idx = ((b * SSZ) + TT + m) * HD + t;
        g_k[idx] = y;
        g_v[idx] = y;
    }
}

// ---------------------------------------------------------------------------
// Kernel 2: fused QKV projection. GEMM [16384 x 1024] x [1024 x 192].
// Block: 256 threads (16x16), tile 64(M) x 192(N), K-chunks of 32.
// Each thread computes 4x12 outputs. x is read exactly once from HBM.
// Static smem: 33,152 B < 48 KB, fine.
// ---------------------------------------------------------------------------
#define KT 32
__global__ __launch_bounds__(256, 2) void qkv_kernel(
    const float* __restrict__ x,
    const float* __restrict__ Wq,
    const float* __restrict__ Wk,
    const float* __restrict__ Wv) {

    __shared__ float xs[64][KT + 1];    // pad -> conflict-light
    __shared__ float ws[KT][193];       // 192 cols (q|k|v) + pad

    int tid = threadIdx.x;
    int tx = tid & 15;                  // N direction
    int ty = tid >> 4;                  // M direction
    int row0 = blockIdx.x * 64;

    float acc[4][12];
    #pragma unroll
    for (int i = 0; i < 4; i++)
        #pragma unroll
        for (int j = 0; j < 12; j++) acc[i][j] = 0.0f;

    for (int k0 = 0; k0 < DD; k0 += KT) {
        // load x tile: 64x32 floats via float4 gmem loads, scalar smem stores
        #pragma unroll
        for (int i = 0; i < 2; i++) {
            int idx = tid + i * 256;          // 0..511 quads
            int r = idx >> 3;                 // 8 quads per row
            int q = idx & 7;
            float4 val = *(const float4*)&x[(size_t)(row0 + r) * DD + k0 + q * 4];
            xs[r][q * 4 + 0] = val.x;
            xs[r][q * 4 + 1] = val.y;
            xs[r][q * 4 + 2] = val.z;
            xs[r][q * 4 + 3] = val.w;
        }
        // load W tiles (32x64 each, q|k|v side by side)
        #pragma unroll
        for (int i = 0; i < 2; i++) {
            int idx = tid + i * 256;          // 0..511 quads per matrix
            int r = idx >> 4;                 // 16 quads per row
            int q = idx & 15;
            float4 aq = *(const float4*)&Wq[(size_t)(k0 + r) * HD + q * 4];
            float4 ak = *(const float4*)&Wk[(size_t)(k0 + r) * HD + q * 4];
            float4 av = *(const float4*)&Wv[(size_t)(k0 + r) * HD + q * 4];
            int c = q * 4;
            ws[r][c + 0] = aq.x; ws[r][c + 1] = aq.y; ws[r][c + 2] = aq.z; ws[r][c + 3] = aq.w;
            ws[r][64 + c + 0] = ak.x; ws[r][64 + c + 1] = ak.y; ws[r][64 + c + 2] = ak.z; ws[r][64 + c + 3] = ak.w;
            ws[r][128 + c + 0] = av.x; ws[r][128 + c + 1] = av.y; ws[r][128 + c + 2] = av.z; ws[r][128 + c + 3] = av.w;
        }
        __syncthreads();

        #pragma unroll
        for (int k = 0; k < KT; k++) {
            float a[4];
            #pragma unroll
            for (int i = 0; i < 4; i++) a[i] = xs[ty * 4 + i][k];
            float bv[12];
            #pragma unroll
            for (int j = 0; j < 12; j++) bv[j] = ws[k][tx * 12 + j];
            #pragma unroll
            for (int i = 0; i < 4; i++)
                #pragma unroll
                for (int j = 0; j < 12; j++)
                    acc[i][j] = fmaf(a[i], bv[j], acc[i][j]);
        }
        __syncthreads();
    }

    // Epilogue: scatter into g_q (prescaled), g_k, g_v
    #pragma unroll
    for (int i = 0; i < 4; i++) {
        int r = row0 + ty * 4 + i;            // global row in [0, BT)
        int b = r / TT;
        int rr = r % TT;
        #pragma unroll
        for (int j = 0; j < 12; j++) {
            int col = tx * 12 + j;
            float val = acc[i][j];
            if (col < 64) {
                g_q[(size_t)r * HD + col] = val * 0.125f;   // d^-0.5 = 1/8
            } else if (col < 128) {
                g_k[((size_t)b * SSZ + rr) * HD + (col - 64)] = val;
            } else {
                g_v[((size_t)b * SSZ + rr) * HD + (col - 128)] = val;
            }
        }
    }
}

// ---------------------------------------------------------------------------
// Kernel 3: flash attention. Block handles 64 queries of one batch;
// loops over 33 key tiles of 64, online softmax, fp32 accumulators.
// 256 threads (16x16), 4x4 register tile each for both GEMM phases.
// Shared memory is DYNAMIC (67,328 B > 48 KB static limit); layout:
//   qs[64][65] | ks[64][65] | vs[64][65] | ss[64][65] | mrow[64] lrow[64] frow[64]
// ---------------------------------------------------------------------------
#define TP 65                               // padded tile stride (floats)
#define ATTN_SMEM_FLOATS (4 * 64 * TP + 3 * 64)
#define ATTN_SMEM_BYTES  (ATTN_SMEM_FLOATS * 4)

__global__ __launch_bounds__(256, 1) void attn_kernel(float* __restrict__ out) {
    extern __shared__ float sm[];
    float* qs   = sm;                       // [64][TP]
    float* ks   = sm + 64 * TP;             // [64][TP]
    float* vs   = sm + 2 * 64 * TP;         // [64][TP]
    float* ss   = sm + 3 * 64 * TP;         // [64][TP]
    float* mrow = sm + 4 * 64 * TP;
    float* lrow = mrow + 64;
    float* frow = lrow + 64;
#define QS(r, c) qs[(r) * TP + (c)]
#define KS(r, c) ks[(r) * TP + (c)]
#define VS(r, c) vs[(r) * TP + (c)]
#define SS(r, c) ss[(r) * TP + (c)]

    int tid = threadIdx.x;
    int tx = tid & 15;
    int ty = tid >> 4;
    int b = blockIdx.y;
    int q0 = blockIdx.x * 64;

    // Load Q tile (already scaled by 1/8)
    #pragma unroll
    for (int i = 0; i < 4; i++) {
        int idx = tid + i * 256;           // 1024 quads = 64x64 floats
        int r = idx >> 4;
        int q = idx & 15;
        float4 val = *(const float4*)&g_q[((size_t)b * TT + q0 + r) * HD + q * 4];
        QS(r, q * 4 + 0) = val.x;
        QS(r, q * 4 + 1) = val.y;
        QS(r, q * 4 + 2) = val.z;
        QS(r, q * 4 + 3) = val.w;
    }
    if (tid < 64) { mrow[tid] = -1e30f; lrow[tid] = 0.0f; }

    float acc[4][4];
    #pragma unroll
    for (int i = 0; i < 4; i++)
        #pragma unroll
        for (int j = 0; j < 4; j++) acc[i][j] = 0.0f;

    for (int s0 = 0; s0 < SSZ; s0 += 64) {
        __syncthreads();   // guards ss/ks/vs reuse + first-iter init
        // load K and V tiles
        #pragma unroll
        for (int i = 0; i < 4; i++) {
            int idx = tid + i * 256;
            int r = idx >> 4;
            int q = idx & 15;
            float4 kk = *(const float4*)&g_k[((size_t)b * SSZ + s0 + r) * HD + q * 4];
            float4 vv = *(const float4*)&g_v[((size_t)b * SSZ + s0 + r) * HD + q * 4];
            int c = q * 4;
            KS(r, c + 0) = kk.x; KS(r, c + 1) = kk.y; KS(r, c + 2) = kk.z; KS(r, c + 3) = kk.w;
            VS(r, c + 0) = vv.x; VS(r, c + 1) = vv.y; VS(r, c + 2) = vv.z; VS(r, c + 3) = vv.w;
        }
        __syncthreads();

        // Phase A: S = Q * K^T  (64x64 tile, 4x4 per thread)
        float sc[4][4];
        #pragma unroll
        for (int i = 0; i < 4; i++)
            #pragma unroll
            for (int j = 0; j < 4; j++) sc[i][j] = 0.0f;
        #pragma unroll 8
        for (int k = 0; k < HD; k++) {
            float a[4], bb[4];
            #pragma unroll
            for (int i = 0; i < 4; i++) a[i] = QS(ty * 4 + i, k);
            #pragma unroll
            for (int j = 0; j < 4; j++) bb[j] = KS(tx * 4 + j, k);
            #pragma unroll
            for (int i = 0; i < 4; i++)
                #pragma unroll
                for (int j = 0; j < 4; j++)
                    sc[i][j] = fmaf(a[i], bb[j], sc[i][j]);
        }
        #pragma unroll
        for (int i = 0; i < 4; i++)
            #pragma unroll
            for (int j = 0; j < 4; j++)
                SS(ty * 4 + i, tx * 4 + j) = sc[i][j];
        __syncthreads();

        // Phase B: online softmax. Thread group of 4 lanes per row.
        {
            int r = tid >> 2;
            int c0 = (tid & 3) * 16;
            float lm = -1e30f;
            #pragma unroll
            for (int c = 0; c < 16; c++) lm = fmaxf(lm, SS(r, c0 + c));
            lm = fmaxf(lm, __shfl_xor_sync(0xffffffffu, lm, 1));
            lm = fmaxf(lm, __shfl_xor_sync(0xffffffffu, lm, 2));
            float mold = mrow[r];
            float mnew = fmaxf(mold, lm);
            float lsum = 0.0f;
            #pragma unroll
            for (int c = 0; c < 16; c++) {
                float p = __expf(SS(r, c0 + c) - mnew);
                SS(r, c0 + c) = p;
                lsum += p;
            }
            lsum += __shfl_xor_sync(0xffffffffu, lsum, 1);
            lsum += __shfl_xor_sync(0xffffffffu, lsum, 2);
            if ((tid & 3) == 0) {
                float f = __expf(mold - mnew);
                frow[r] = f;
                lrow[r] = lrow[r] * f + lsum;
                mrow[r] = mnew;
            }
        }
        __syncthreads();

        // Phase C: O = O*f + P * V
        float f[4];
        #pragma unroll
        for (int i = 0; i < 4; i++) f[i] = frow[ty * 4 + i];
        #pragma unroll
        for (int i = 0; i < 4; i++)
            #pragma unroll
            for (int j = 0; j < 4; j++) acc[i][j] *= f[i];
        #pragma unroll 8
        for (int k = 0; k < 64; k++) {
            float p[4], vv[4];
            #pragma unroll
            for (int i = 0; i < 4; i++) p[i] = SS(ty * 4 + i, k);
            #pragma unroll
            for (int j = 0; j < 4; j++) vv[j] = VS(k, tx * 4 + j);
            #pragma unroll
            for (int i = 0; i < 4; i++)
                #pragma unroll
                for (int j = 0; j < 4; j++)
                    acc[i][j] = fmaf(p[i], vv[j], acc[i][j]);
        }
    }

    // Epilogue: divide by l and store
    #pragma unroll
    for (int i = 0; i < 4; i++) {
        int r = ty * 4 + i;
        float inv = 1.0f / lrow[r];
        size_t base = ((size_t)b * TT + q0 + r) * HD + tx * 4;
        #pragma unroll
        for (int j = 0; j < 4; j++)
            out[base + j] = acc[i][j] * inv;
    }
}

// ---------------------------------------------------------------------------
extern "C" void kernel_launch(void* const* d_in, const int* in_sizes, int n_in,
                              void* d_out, int out_size) {
    const float* x      = (const float*)d_in[0];  // [8,2048,1024]
    const float* c_emb  = (const float*)d_in[1];  // [64,64]
    const float* Wq     = (const float*)d_in[2];  // [1024,64]
    const float* Wk     = (const float*)d_in[3];
    const float* Wv     = (const float*)d_in[4];
    const float* gamma  = (const float*)d_in[5];  // [64]
    const float* beta   = (const float*)d_in[6];  // [64]
    float* out          = (float*)d_out;          // [8,2048,64]

    (void)in_sizes; (void)n_in; (void)out_size;

    // Opt in to >48KB dynamic smem for the attention kernel. Host-side,
    // non-allocating, non-stream API: runs at capture time only, creates no
    // graph node, idempotent.
    cudaFuncSetAttribute(attn_kernel,
                         cudaFuncAttributeMaxDynamicSharedMemorySize,
                         ATTN_SMEM_BYTES);

    ln_kernel<<<MM, 64>>>(c_emb, gamma, beta);
    qkv_kernel<<<BT / 64, 256>>>(x, Wq, Wk, Wv);
    dim3 agrid(TT / 64, BB);
    attn_kernel<<<agrid, 256, ATTN_SMEM_BYTES>>>(out);
}

// round 5
// speedup vs baseline: 2.0744x; 2.0744x over previous
#include <cuda_runtime.h>
#include <math.h>

// Problem dims (fixed by reference)
#define BB 8
#define TT 2048
#define DD 1024
#define HD 64
#define MM 64
#define SSZ (TT + MM)          // 2112 keys/values per batch
#define BT (BB * TT)           // 16384 query rows total

// d^-0.5 * log2(e): logits produced directly in log2 domain
#define SCALE_Q 0.18033688011112042f

// Scratch (allocation-free rule: __device__ globals)
// All three hold tf32-rounded values (exact in fp32).
__device__ float g_q[BT * HD];          // prescaled by d^-0.5*log2e
__device__ float g_k[BB * SSZ * HD];
__device__ float g_v[BB * SSZ * HD];

// ---------------------------------------------------------------------------
// Helpers: tf32 rounding (RNA) + warp mma m16n8k8 tf32
// ---------------------------------------------------------------------------
__device__ __forceinline__ unsigned tf32u(float x) {
    unsigned u;
    asm("cvt.rna.tf32.f32 %0, %1;" : "=r"(u) : "f"(x));
    return u;
}
__device__ __forceinline__ float tf32r(float x) {
    return __uint_as_float(tf32u(x));
}
__device__ __forceinline__ void mma8(float* c,
                                     unsigned a0, unsigned a1, unsigned a2, unsigned a3,
                                     unsigned b0, unsigned b1) {
    asm volatile(
        "mma.sync.aligned.m16n8k8.row.col.f32.tf32.tf32.f32 "
        "{%0,%1,%2,%3},{%4,%5,%6,%7},{%8,%9},{%0,%1,%2,%3};"
        : "+f"(c[0]), "+f"(c[1]), "+f"(c[2]), "+f"(c[3])
        : "r"(a0), "r"(a1), "r"(a2), "r"(a3), "r"(b0), "r"(b1));
}

// 2^y for y <= 0, FMA-pipe only (no MUFU). |rel err| ~1e-7.
__device__ __forceinline__ float exp2_poly(float y) {
    y = fmaxf(y, -120.0f);
    float fl = floorf(y);
    float f = y - fl;
    float p = 0.0018775767f;
    p = fmaf(p, f, 0.0089893397f);
    p = fmaf(p, f, 0.055826318f);
    p = fmaf(p, f, 0.24015361f);
    p = fmaf(p, f, 0.69315308f);
    p = fmaf(p, f, 0.99999994f);
    float s = __int_as_float(((int)fl + 127) << 23);
    return p * s;
}

// ---------------------------------------------------------------------------
// Kernel 1: layernorm(c_emb) -> broadcast (tf32-rounded) into g_k/g_v tails
// ---------------------------------------------------------------------------
__global__ void ln_kernel(const float* __restrict__ c_emb,
                          const float* __restrict__ gamma,
                          const float* __restrict__ beta) {
    int m = blockIdx.x;
    int t = threadIdx.x;
    __shared__ float red[64];

    float v = c_emb[m * HD + t];
    red[t] = v;
    __syncthreads();
    for (int off = 32; off > 0; off >>= 1) {
        if (t < off) red[t] += red[t + off];
        __syncthreads();
    }
    float mu = red[0] * (1.0f / HD);
    __syncthreads();
    float dv = v - mu;
    red[t] = dv * dv;
    __syncthreads();
    for (int off = 32; off > 0; off >>= 1) {
        if (t < off) red[t] += red[t + off];
        __syncthreads();
    }
    float var = red[0] * (1.0f / HD);
    float y = tf32r(dv * rsqrtf(var + 1e-5f) * gamma[t] + beta[t]);

    #pragma unroll
    for (int b = 0; b < BB; b++) {
        int idx = ((b * SSZ) + TT + m) * HD + t;
        g_k[idx] = y;
        g_v[idx] = y;
    }
}

// ---------------------------------------------------------------------------
// Kernel 2: fused QKV projection via tf32 mma.
// GEMM [16384 x 1024] x [1024 x 192]. Block tile 64(M) x 192(N), K-chunk 32.
// 8 warps: 4(M) x 2(N); warp = 16 rows x 96 cols (12 n8 tiles).
// Smem strides = 4 (mod 32): fragment loads conflict-free.
// ---------------------------------------------------------------------------
#define XS_ST 36
#define WS_ST 196
__global__ __launch_bounds__(256) void qkv_kernel(
    const float* __restrict__ x,
    const float* __restrict__ Wq,
    const float* __restrict__ Wk,
    const float* __restrict__ Wv) {

    __shared__ float xs[64][XS_ST];
    __shared__ float ws[32][WS_ST];

    int tid = threadIdx.x;
    int lane = tid & 31;
    int wid = tid >> 5;
    int wm = wid & 3;          // warp row group (16 rows)
    int wn = wid >> 2;         // warp col group (96 cols)
    int g = lane >> 2;
    int t = lane & 3;
    int row0 = blockIdx.x * 64;

    float acc[12][4];
    #pragma unroll
    for (int n = 0; n < 12; n++)
        #pragma unroll
        for (int i = 0; i < 4; i++) acc[n][i] = 0.0f;

    for (int k0 = 0; k0 < DD; k0 += 32) {
        // x tile 64x32 (tf32-rounded)
        #pragma unroll
        for (int i = 0; i < 2; i++) {
            int idx = tid + i * 256;
            int r = idx >> 3;
            int q = idx & 7;
            float4 v = *(const float4*)&x[(size_t)(row0 + r) * DD + k0 + q * 4];
            xs[r][q * 4 + 0] = tf32r(v.x);
            xs[r][q * 4 + 1] = tf32r(v.y);
            xs[r][q * 4 + 2] = tf32r(v.z);
            xs[r][q * 4 + 3] = tf32r(v.w);
        }
        // W tiles 32x64 each (q|k|v)
        #pragma unroll
        for (int i = 0; i < 2; i++) {
            int idx = tid + i * 256;
            int r = idx >> 4;
            int q = idx & 15;
            int c = q * 4;
            float4 aq = *(const float4*)&Wq[(size_t)(k0 + r) * HD + c];
            float4 ak = *(const float4*)&Wk[(size_t)(k0 + r) * HD + c];
            float4 av = *(const float4*)&Wv[(size_t)(k0 + r) * HD + c];
            ws[r][c + 0] = tf32r(aq.x); ws[r][c + 1] = tf32r(aq.y);
            ws[r][c + 2] = tf32r(aq.z); ws[r][c + 3] = tf32r(aq.w);
            ws[r][64 + c + 0] = tf32r(ak.x); ws[r][64 + c + 1] = tf32r(ak.y);
            ws[r][64 + c + 2] = tf32r(ak.z); ws[r][64 + c + 3] = tf32r(ak.w);
            ws[r][128 + c + 0] = tf32r(av.x); ws[r][128 + c + 1] = tf32r(av.y);
            ws[r][128 + c + 2] = tf32r(av.z); ws[r][128 + c + 3] = tf32r(av.w);
        }
        __syncthreads();

        #pragma unroll
        for (int kk = 0; kk < 4; kk++) {
            int kb = kk * 8;
            unsigned a0 = __float_as_uint(xs[wm * 16 + g][kb + t]);
            unsigned a1 = __float_as_uint(xs[wm * 16 + g + 8][kb + t]);
            unsigned a2 = __float_as_uint(xs[wm * 16 + g][kb + t + 4]);
            unsigned a3 = __float_as_uint(xs[wm * 16 + g + 8][kb + t + 4]);
            #pragma unroll
            for (int n = 0; n < 12; n++) {
                int nc = wn * 96 + n * 8;
                unsigned b0 = __float_as_uint(ws[kb + t][nc + g]);
                unsigned b1 = __float_as_uint(ws[kb + t + 4][nc + g]);
                mma8(acc[n], a0, a1, a2, a3, b0, b1);
            }
        }
        __syncthreads();
    }

    // Epilogue: scatter (tf32-rounded) into g_q (prescaled), g_k, g_v
    int r0 = row0 + wm * 16 + g;          // rows r0, r0+8
    #pragma unroll
    for (int n = 0; n < 12; n++) {
        int nc = wn * 96 + n * 8;
        int mat = nc >> 6;                // 0=q, 1=k, 2=v (8-wide tiles never straddle)
        int lc = (nc & 63) + 2 * t;
        #pragma unroll
        for (int h = 0; h < 2; h++) {     // h=0 -> row r0 (c0,c1), h=1 -> row r0+8 (c2,c3)
            int r = r0 + h * 8;
            float v0 = acc[n][h * 2 + 0];
            float v1 = acc[n][h * 2 + 1];
            if (mat == 0) {
                float2 o = make_float2(tf32r(v0 * SCALE_Q), tf32r(v1 * SCALE_Q));
                *(float2*)&g_q[(size_t)r * HD + lc] = o;
            } else {
                int b = r >> 11;          // r / TT
                int rr = r & 2047;        // r % TT
                float2 o = make_float2(tf32r(v0), tf32r(v1));
                if (mat == 1) *(float2*)&g_k[((size_t)b * SSZ + rr) * HD + lc] = o;
                else          *(float2*)&g_v[((size_t)b * SSZ + rr) * HD + lc] = o;
            }
        }
    }
}

// ---------------------------------------------------------------------------
// Kernel 3: flash attention with tf32 mma + FMA-pipe log2-domain softmax.
// Block = 64 queries; loop over 33 key tiles of 64.
// 8 warps: 4(M) x 2(N); warp = 16 rows x 32 cols (4 n8 tiles).
// Dynamic smem, tile stride 68 (= 4 mod 32 -> conflict-free fragment loads).
// ---------------------------------------------------------------------------
#define TP 68
#define ATTN_SMEM_FLOATS (4 * 64 * TP + 3 * 64)
#define ATTN_SMEM_BYTES  (ATTN_SMEM_FLOATS * 4)

__global__ __launch_bounds__(256) void attn_kernel(float* __restrict__ out) {
    extern __shared__ float sm[];
    float* qs   = sm;                       // [64][TP]
    float* ks   = sm + 64 * TP;
    float* vs   = sm + 2 * 64 * TP;
    float* ss   = sm + 3 * 64 * TP;
    float* mrow = sm + 4 * 64 * TP;
    float* lrow = mrow + 64;
    float* frow = lrow + 64;
#define QS(r, c) qs[(r) * TP + (c)]
#define KS(r, c) ks[(r) * TP + (c)]
#define VS(r, c) vs[(r) * TP + (c)]
#define SS(r, c) ss[(r) * TP + (c)]

    int tid = threadIdx.x;
    int lane = tid & 31;
    int wid = tid >> 5;
    int wm = wid & 3;
    int wn = wid >> 2;
    int g = lane >> 2;
    int t = lane & 3;
    int b = blockIdx.y;
    int q0 = blockIdx.x * 64;

    // Load Q tile (tf32-rounded, prescaled by d^-0.5*log2e)
    #pragma unroll
    for (int i = 0; i < 4; i++) {
        int idx = tid + i * 256;
        int r = idx >> 4;
        int q = idx & 15;
        float4 v = *(const float4*)&g_q[((size_t)b * TT + q0 + r) * HD + q * 4];
        *(float4*)&QS(r, q * 4) = v;
    }
    if (tid < 64) { mrow[tid] = -1e30f; lrow[tid] = 0.0f; }

    float acc[4][4];
    #pragma unroll
    for (int n = 0; n < 4; n++)
        #pragma unroll
        for (int i = 0; i < 4; i++) acc[n][i] = 0.0f;

    for (int s0 = 0; s0 < SSZ; s0 += 64) {
        __syncthreads();   // guards ks/vs/ss reuse + first-iter init
        // Load K and V tiles
        #pragma unroll
        for (int i = 0; i < 4; i++) {
            int idx = tid + i * 256;
            int r = idx >> 4;
            int q = idx & 15;
            float4 kk = *(const float4*)&g_k[((size_t)b * SSZ + s0 + r) * HD + q * 4];
            float4 vv = *(const float4*)&g_v[((size_t)b * SSZ + s0 + r) * HD + q * 4];
            *(float4*)&KS(r, q * 4) = kk;
            *(float4*)&VS(r, q * 4) = vv;
        }
        __syncthreads();

        // Phase A: S = Q * K^T via mma (warp: 16x32)
        float sc[4][4];
        #pragma unroll
        for (int n = 0; n < 4; n++)
            #pragma unroll
            for (int i = 0; i < 4; i++) sc[n][i] = 0.0f;
        #pragma unroll
        for (int kk = 0; kk < 8; kk++) {
            int kb = kk * 8;
            unsigned a0 = __float_as_uint(QS(wm * 16 + g, kb + t));
            unsigned a1 = __float_as_uint(QS(wm * 16 + g + 8, kb + t));
            unsigned a2 = __float_as_uint(QS(wm * 16 + g, kb + t + 4));
            unsigned a3 = __float_as_uint(QS(wm * 16 + g + 8, kb + t + 4));
            #pragma unroll
            for (int n = 0; n < 4; n++) {
                int nc = wn * 32 + n * 8;
                unsigned b0 = __float_as_uint(KS(nc + g, kb + t));
                unsigned b1 = __float_as_uint(KS(nc + g, kb + t + 4));
                mma8(sc[n], a0, a1, a2, a3, b0, b1);
            }
        }
        #pragma unroll
        for (int n = 0; n < 4; n++) {
            int col = wn * 32 + n * 8 + 2 * t;
            *(float2*)&SS(wm * 16 + g, col)     = make_float2(sc[n][0], sc[n][1]);
            *(float2*)&SS(wm * 16 + g + 8, col) = make_float2(sc[n][2], sc[n][3]);
        }
        __syncthreads();

        // Phase B: online softmax in log2 domain, FMA-pipe exp2
        {
            int r = tid >> 2;
            int c0 = (tid & 3) * 16;
            float lm = -1e30f;
            #pragma unroll
            for (int c = 0; c < 16; c++) lm = fmaxf(lm, SS(r, c0 + c));
            lm = fmaxf(lm, __shfl_xor_sync(0xffffffffu, lm, 1));
            lm = fmaxf(lm, __shfl_xor_sync(0xffffffffu, lm, 2));
            float mold = mrow[r];
            float mnew = fmaxf(mold, lm);
            float lsum = 0.0f;
            #pragma unroll
            for (int c = 0; c < 16; c++) {
                float p = exp2_poly(SS(r, c0 + c) - mnew);
                SS(r, c0 + c) = p;
                lsum += p;
            }
            lsum += __shfl_xor_sync(0xffffffffu, lsum, 1);
            lsum += __shfl_xor_sync(0xffffffffu, lsum, 2);
            if ((tid & 3) == 0) {
                float f = exp2_poly(mold - mnew);
                frow[r] = f;
                lrow[r] = lrow[r] * f + lsum;
                mrow[r] = mnew;
            }
        }
        __syncthreads();

        // Phase C: O = O*f + P*V via mma (warp: 16x32)
        float fa = frow[wm * 16 + g];
        float fb = frow[wm * 16 + g + 8];
        #pragma unroll
        for (int n = 0; n < 4; n++) {
            acc[n][0] *= fa; acc[n][1] *= fa;
            acc[n][2] *= fb; acc[n][3] *= fb;
        }
        #pragma unroll
        for (int kk = 0; kk < 8; kk++) {
            int kb = kk * 8;
            unsigned a0 = tf32u(SS(wm * 16 + g, kb + t));
            unsigned a1 = tf32u(SS(wm * 16 + g + 8, kb + t));
            unsigned a2 = tf32u(SS(wm * 16 + g, kb + t + 4));
            unsigned a3 = tf32u(SS(wm * 16 + g + 8, kb + t + 4));
            #pragma unroll
            for (int n = 0; n < 4; n++) {
                int nc = wn * 32 + n * 8;
                unsigned b0 = __float_as_uint(VS(kb + t, nc + g));
                unsigned b1 = __float_as_uint(VS(kb + t + 4, nc + g));
                mma8(acc[n], a0, a1, a2, a3, b0, b1);
            }
        }
    }

    // Epilogue: normalize by l and store
    float ia = 1.0f / lrow[wm * 16 + g];
    float ib = 1.0f / lrow[wm * 16 + g + 8];
    #pragma unroll
    for (int n = 0; n < 4; n++) {
        int col = wn * 32 + n * 8 + 2 * t;
        int ra = q0 + wm * 16 + g;
        int rb = ra + 8;
        *(float2*)&out[((size_t)b * TT + ra) * HD + col] =
            make_float2(acc[n][0] * ia, acc[n][1] * ia);
        *(float2*)&out[((size_t)b * TT + rb) * HD + col] =
            make_float2(acc[n][2] * ib, acc[n][3] * ib);
    }
}

// ---------------------------------------------------------------------------
extern "C" void kernel_launch(void* const* d_in, const int* in_sizes, int n_in,
                              void* d_out, int out_size) {
    const float* x      = (const float*)d_in[0];  // [8,2048,1024]
    const float* c_emb  = (const float*)d_in[1];  // [64,64]
    const float* Wq     = (const float*)d_in[2];  // [1024,64]
    const float* Wk     = (const float*)d_in[3];
    const float* Wv     = (const float*)d_in[4];
    const float* gamma  = (const float*)d_in[5];  // [64]
    const float* beta   = (const float*)d_in[6];  // [64]
    float* out          = (float*)d_out;          // [8,2048,64]

    (void)in_sizes; (void)n_in; (void)out_size;

    cudaFuncSetAttribute(attn_kernel,
                         cudaFuncAttributeMaxDynamicSharedMemorySize,
                         ATTN_SMEM_BYTES);

    ln_kernel<<<MM, 64>>>(c_emb, gamma, beta);
    qkv_kernel<<<BT / 64, 256>>>(x, Wq, Wk, Wv);
    dim3 agrid(TT / 64, BB);
    attn_kernel<<<agrid, 256, ATTN_SMEM_BYTES>>>(out);
}

// round 6
// speedup vs baseline: 2.3217x; 1.1192x over previous
#include <cuda_runtime.h>
#include <math.h>

// Problem dims (fixed by reference)
#define BB 8
#define TT 2048
#define DD 1024
#define HD 64
#define MM 64
#define SSZ (TT + MM)          // 2112 keys/values per batch
#define BT (BB * TT)           // 16384 query rows total

// d^-0.5 * log2(e): logits produced directly in log2 domain
#define SCALE_Q 0.18033688011112042f

// Scratch (allocation-free rule: __device__ globals)
// All three hold tf32-rounded values (exact in fp32).
__device__ float g_q[BT * HD];          // prescaled by d^-0.5*log2e
__device__ float g_k[BB * SSZ * HD];
__device__ float g_v[BB * SSZ * HD];

// ---------------------------------------------------------------------------
// Helpers
// ---------------------------------------------------------------------------
__device__ __forceinline__ unsigned tf32u(float x) {
    unsigned u;
    asm("cvt.rna.tf32.f32 %0, %1;" : "=r"(u) : "f"(x));
    return u;
}
__device__ __forceinline__ float tf32r(float x) {
    return __uint_as_float(tf32u(x));
}
__device__ __forceinline__ void mma8(float* c,
                                     unsigned a0, unsigned a1, unsigned a2, unsigned a3,
                                     unsigned b0, unsigned b1) {
    asm volatile(
        "mma.sync.aligned.m16n8k8.row.col.f32.tf32.tf32.f32 "
        "{%0,%1,%2,%3},{%4,%5,%6,%7},{%8,%9},{%0,%1,%2,%3};"
        : "+f"(c[0]), "+f"(c[1]), "+f"(c[2]), "+f"(c[3])
        : "r"(a0), "r"(a1), "r"(a2), "r"(a3), "r"(b0), "r"(b1));
}

// 2^y for y <= 0, FMA-pipe only (no MUFU). |rel err| ~1e-7.
__device__ __forceinline__ float exp2_poly(float y) {
    y = fmaxf(y, -120.0f);
    float fl = floorf(y);
    float f = y - fl;
    float p = 0.0018775767f;
    p = fmaf(p, f, 0.0089893397f);
    p = fmaf(p, f, 0.055826318f);
    p = fmaf(p, f, 0.24015361f);
    p = fmaf(p, f, 0.69315308f);
    p = fmaf(p, f, 0.99999994f);
    float s = __int_as_float(((int)fl + 127) << 23);
    return p * s;
}

__device__ __forceinline__ void cp16(void* smem_dst, const void* gmem_src) {
    unsigned s = (unsigned)__cvta_generic_to_shared(smem_dst);
    asm volatile("cp.async.cg.shared.global [%0], [%1], 16;"
                 :: "r"(s), "l"(gmem_src));
}
#define CP_COMMIT() asm volatile("cp.async.commit_group;" ::: "memory")
#define CP_WAIT0()  asm volatile("cp.async.wait_group 0;" ::: "memory")

// ---------------------------------------------------------------------------
// Kernel 1: layernorm(c_emb) -> broadcast (tf32-rounded) into g_k/g_v tails
// ---------------------------------------------------------------------------
__global__ void ln_kernel(const float* __restrict__ c_emb,
                          const float* __restrict__ gamma,
                          const float* __restrict__ beta) {
    int m = blockIdx.x;
    int t = threadIdx.x;
    __shared__ float red[64];

    float v = c_emb[m * HD + t];
    red[t] = v;
    __syncthreads();
    for (int off = 32; off > 0; off >>= 1) {
        if (t < off) red[t] += red[t + off];
        __syncthreads();
    }
    float mu = red[0] * (1.0f / HD);
    __syncthreads();
    float dv = v - mu;
    red[t] = dv * dv;
    __syncthreads();
    for (int off = 32; off > 0; off >>= 1) {
        if (t < off) red[t] += red[t + off];
        __syncthreads();
    }
    float var = red[0] * (1.0f / HD);
    float y = tf32r(dv * rsqrtf(var + 1e-5f) * gamma[t] + beta[t]);

    #pragma unroll
    for (int b = 0; b < BB; b++) {
        int idx = ((b * SSZ) + TT + m) * HD + t;
        g_k[idx] = y;
        g_v[idx] = y;
    }
}

// ---------------------------------------------------------------------------
// Kernel 2: fused QKV projection via tf32 mma (unchanged from R5).
// ---------------------------------------------------------------------------
#define XS_ST 36
#define WS_ST 196
__global__ __launch_bounds__(256) void qkv_kernel(
    const float* __restrict__ x,
    const float* __restrict__ Wq,
    const float* __restrict__ Wk,
    const float* __restrict__ Wv) {

    __shared__ float xs[64][XS_ST];
    __shared__ float ws[32][WS_ST];

    int tid = threadIdx.x;
    int lane = tid & 31;
    int wid = tid >> 5;
    int wm = wid & 3;
    int wn = wid >> 2;
    int g = lane >> 2;
    int t = lane & 3;
    int row0 = blockIdx.x * 64;

    float acc[12][4];
    #pragma unroll
    for (int n = 0; n < 12; n++)
        #pragma unroll
        for (int i = 0; i < 4; i++) acc[n][i] = 0.0f;

    for (int k0 = 0; k0 < DD; k0 += 32) {
        #pragma unroll
        for (int i = 0; i < 2; i++) {
            int idx = tid + i * 256;
            int r = idx >> 3;
            int q = idx & 7;
            float4 v = *(const float4*)&x[(size_t)(row0 + r) * DD + k0 + q * 4];
            xs[r][q * 4 + 0] = tf32r(v.x);
            xs[r][q * 4 + 1] = tf32r(v.y);
            xs[r][q * 4 + 2] = tf32r(v.z);
            xs[r][q * 4 + 3] = tf32r(v.w);
        }
        #pragma unroll
        for (int i = 0; i < 2; i++) {
            int idx = tid + i * 256;
            int r = idx >> 4;
            int q = idx & 15;
            int c = q * 4;
            float4 aq = *(const float4*)&Wq[(size_t)(k0 + r) * HD + c];
            float4 ak = *(const float4*)&Wk[(size_t)(k0 + r) * HD + c];
            float4 av = *(const float4*)&Wv[(size_t)(k0 + r) * HD + c];
            ws[r][c + 0] = tf32r(aq.x); ws[r][c + 1] = tf32r(aq.y);
            ws[r][c + 2] = tf32r(aq.z); ws[r][c + 3] = tf32r(aq.w);
            ws[r][64 + c + 0] = tf32r(ak.x); ws[r][64 + c + 1] = tf32r(ak.y);
            ws[r][64 + c + 2] = tf32r(ak.z); ws[r][64 + c + 3] = tf32r(ak.w);
            ws[r][128 + c + 0] = tf32r(av.x); ws[r][128 + c + 1] = tf32r(av.y);
            ws[r][128 + c + 2] = tf32r(av.z); ws[r][128 + c + 3] = tf32r(av.w);
        }
        __syncthreads();

        #pragma unroll
        for (int kk = 0; kk < 4; kk++) {
            int kb = kk * 8;
            unsigned a0 = __float_as_uint(xs[wm * 16 + g][kb + t]);
            unsigned a1 = __float_as_uint(xs[wm * 16 + g + 8][kb + t]);
            unsigned a2 = __float_as_uint(xs[wm * 16 + g][kb + t + 4]);
            unsigned a3 = __float_as_uint(xs[wm * 16 + g + 8][kb + t + 4]);
            #pragma unroll
            for (int n = 0; n < 12; n++) {
                int nc = wn * 96 + n * 8;
                unsigned b0 = __float_as_uint(ws[kb + t][nc + g]);
                unsigned b1 = __float_as_uint(ws[kb + t + 4][nc + g]);
                mma8(acc[n], a0, a1, a2, a3, b0, b1);
            }
        }
        __syncthreads();
    }

    int r0 = row0 + wm * 16 + g;
    #pragma unroll
    for (int n = 0; n < 12; n++) {
        int nc = wn * 96 + n * 8;
        int mat = nc >> 6;
        int lc = (nc & 63) + 2 * t;
        #pragma unroll
        for (int h = 0; h < 2; h++) {
            int r = r0 + h * 8;
            float v0 = acc[n][h * 2 + 0];
            float v1 = acc[n][h * 2 + 1];
            if (mat == 0) {
                float2 o = make_float2(tf32r(v0 * SCALE_Q), tf32r(v1 * SCALE_Q));
                *(float2*)&g_q[(size_t)r * HD + lc] = o;
            } else {
                int b = r >> 11;
                int rr = r & 2047;
                float2 o = make_float2(tf32r(v0), tf32r(v1));
                if (mat == 1) *(float2*)&g_k[((size_t)b * SSZ + rr) * HD + lc] = o;
                else          *(float2*)&g_v[((size_t)b * SSZ + rr) * HD + lc] = o;
            }
        }
    }
}

// ---------------------------------------------------------------------------
// Kernel 3: flash attention, 128 queries/CTA, cp.async double-buffered K/V.
// Grid = (16, 8) = 128 CTAs (single wave). 8 warps: 4(M: 32 rows) x 2(N: 32).
// Warp tile 32x32 per GEMM phase: B fragments reused across 2 M-tiles.
// ---------------------------------------------------------------------------
#define TP2 68                               // stride = 4 (mod 32)
#define KVB (64 * TP2)                       // one K or V buffer (floats)
#define ATTN_SMEM_FLOATS (2 * 128 * TP2 + 4 * KVB + 3 * 128)
#define ATTN_SMEM_BYTES  (ATTN_SMEM_FLOATS * 4)

__global__ __launch_bounds__(256) void attn_kernel(float* __restrict__ out) {
    extern __shared__ float sm[];
    float* qs   = sm;                        // [128][TP2]
    float* ss   = sm + 128 * TP2;            // [128][TP2]
    float* ks   = sm + 2 * 128 * TP2;        // 2 x [64][TP2]
    float* vs   = ks + 2 * KVB;              // 2 x [64][TP2]
    float* mrow = vs + 2 * KVB;              // [128]
    float* lrow = mrow + 128;
    float* frow = lrow + 128;
#define QS(r, c) qs[(r) * TP2 + (c)]
#define SS(r, c) ss[(r) * TP2 + (c)]

    int tid = threadIdx.x;
    int lane = tid & 31;
    int wid = tid >> 5;
    int wm = wid & 3;                        // 32-row group
    int wn = wid >> 2;                       // 32-col group
    int g = lane >> 2;
    int t = lane & 3;
    int b = blockIdx.y;
    int q0 = blockIdx.x * 128;

    // Load Q tile 128x64 (tf32-rounded, prescaled)
    #pragma unroll
    for (int i = 0; i < 8; i++) {
        int idx = tid + i * 256;
        int r = idx >> 4;
        int q = idx & 15;
        float4 v = *(const float4*)&g_q[((size_t)b * TT + q0 + r) * HD + q * 4];
        *(float4*)&QS(r, q * 4) = v;
    }
    if (tid < 128) { mrow[tid] = -1e30f; lrow[tid] = 0.0f; }

    // Prologue: async-load K/V tile 0 into buffer 0
    {
        #pragma unroll
        for (int it = 0; it < 4; it++) {
            int idx = tid + it * 256;
            int r = idx >> 4;
            int q = idx & 15;
            size_t src = ((size_t)b * SSZ + r) * HD + q * 4;
            cp16(ks + r * TP2 + q * 4, &g_k[src]);
            cp16(vs + r * TP2 + q * 4, &g_v[src]);
        }
        CP_COMMIT();
    }

    float acc[2][4][4];
    #pragma unroll
    for (int rt = 0; rt < 2; rt++)
        #pragma unroll
        for (int n = 0; n < 4; n++)
            #pragma unroll
            for (int i = 0; i < 4; i++) acc[rt][n][i] = 0.0f;

    for (int ti = 0; ti < 33; ti++) {
        CP_WAIT0();
        __syncthreads();   // tile ti visible to all; prev iter fully done

        // Kick off next tile into the other buffer (overlaps with compute)
        if (ti < 32) {
            int s0 = (ti + 1) * 64;
            float* kb_ = ks + ((ti + 1) & 1) * KVB;
            float* vb_ = vs + ((ti + 1) & 1) * KVB;
            #pragma unroll
            for (int it = 0; it < 4; it++) {
                int idx = tid + it * 256;
                int r = idx >> 4;
                int q = idx & 15;
                size_t src = ((size_t)b * SSZ + s0 + r) * HD + q * 4;
                cp16(kb_ + r * TP2 + q * 4, &g_k[src]);
                cp16(vb_ + r * TP2 + q * 4, &g_v[src]);
            }
            CP_COMMIT();
        }

        const float* kcur = ks + (ti & 1) * KVB;
        const float* vcur = vs + (ti & 1) * KVB;

        // Phase A: S = Q * K^T  (warp 32x32, B frags shared across 2 M-tiles)
        float sc[2][4][4];
        #pragma unroll
        for (int rt = 0; rt < 2; rt++)
            #pragma unroll
            for (int n = 0; n < 4; n++)
                #pragma unroll
                for (int i = 0; i < 4; i++) sc[rt][n][i] = 0.0f;
        #pragma unroll
        for (int kk = 0; kk < 8; kk++) {
            int kb = kk * 8;
            unsigned a[2][4];
            #pragma unroll
            for (int rt = 0; rt < 2; rt++) {
                int r = wm * 32 + rt * 16 + g;
                a[rt][0] = __float_as_uint(QS(r, kb + t));
                a[rt][1] = __float_as_uint(QS(r + 8, kb + t));
                a[rt][2] = __float_as_uint(QS(r, kb + t + 4));
                a[rt][3] = __float_as_uint(QS(r + 8, kb + t + 4));
            }
            #pragma unroll
            for (int n = 0; n < 4; n++) {
                int nc = wn * 32 + n * 8;
                unsigned b0 = __float_as_uint(kcur[(nc + g) * TP2 + kb + t]);
                unsigned b1 = __float_as_uint(kcur[(nc + g) * TP2 + kb + t + 4]);
                mma8(sc[0][n], a[0][0], a[0][1], a[0][2], a[0][3], b0, b1);
                mma8(sc[1][n], a[1][0], a[1][1], a[1][2], a[1][3], b0, b1);
            }
        }
        #pragma unroll
        for (int rt = 0; rt < 2; rt++) {
            int r = wm * 32 + rt * 16 + g;
            #pragma unroll
            for (int n = 0; n < 4; n++) {
                int col = wn * 32 + n * 8 + 2 * t;
                *(float2*)&SS(r, col)     = make_float2(sc[rt][n][0], sc[rt][n][1]);
                *(float2*)&SS(r + 8, col) = make_float2(sc[rt][n][2], sc[rt][n][3]);
            }
        }
        __syncthreads();

        // Phase B: online softmax (2 threads per row, 32 cols each);
        // P written back tf32-rounded so phase C needs no cvt.
        {
            int r = tid >> 1;
            int c0 = (tid & 1) * 32;
            float lm = -1e30f;
            #pragma unroll
            for (int c = 0; c < 32; c++) lm = fmaxf(lm, SS(r, c0 + c));
            lm = fmaxf(lm, __shfl_xor_sync(0xffffffffu, lm, 1));
            float mold = mrow[r];
            float mnew = fmaxf(mold, lm);
            float lsum = 0.0f;
            #pragma unroll
            for (int c = 0; c < 32; c++) {
                float p = tf32r(exp2_poly(SS(r, c0 + c) - mnew));
                SS(r, c0 + c) = p;
                lsum += p;
            }
            lsum += __shfl_xor_sync(0xffffffffu, lsum, 1);
            if (!(tid & 1)) {
                float f = exp2_poly(mold - mnew);
                frow[r] = f;
                lrow[r] = lrow[r] * f + lsum;
                mrow[r] = mnew;
            }
        }
        __syncthreads();

        // Phase C: O = O*f + P*V (warp 32x32)
        float fr[2][2];
        #pragma unroll
        for (int rt = 0; rt < 2; rt++) {
            fr[rt][0] = frow[wm * 32 + rt * 16 + g];
            fr[rt][1] = frow[wm * 32 + rt * 16 + g + 8];
        }
        #pragma unroll
        for (int rt = 0; rt < 2; rt++)
            #pragma unroll
            for (int n = 0; n < 4; n++) {
                acc[rt][n][0] *= fr[rt][0]; acc[rt][n][1] *= fr[rt][0];
                acc[rt][n][2] *= fr[rt][1]; acc[rt][n][3] *= fr[rt][1];
            }
        #pragma unroll
        for (int kk = 0; kk < 8; kk++) {
            int kb = kk * 8;
            unsigned a[2][4];
            #pragma unroll
            for (int rt = 0; rt < 2; rt++) {
                int r = wm * 32 + rt * 16 + g;
                a[rt][0] = __float_as_uint(SS(r, kb + t));
                a[rt][1] = __float_as_uint(SS(r + 8, kb + t));
                a[rt][2] = __float_as_uint(SS(r, kb + t + 4));
                a[rt][3] = __float_as_uint(SS(r + 8, kb + t + 4));
            }
            #pragma unroll
            for (int n = 0; n < 4; n++) {
                int nc = wn * 32 + n * 8;
                unsigned b0 = __float_as_uint(vcur[(kb + t) * TP2 + nc + g]);
                unsigned b1 = __float_as_uint(vcur[(kb + t + 4) * TP2 + nc + g]);
                mma8(acc[0][n], a[0][0], a[0][1], a[0][2], a[0][3], b0, b1);
                mma8(acc[1][n], a[1][0], a[1][1], a[1][2], a[1][3], b0, b1);
            }
        }
        // no trailing sync: next iter's wait+sync guards buffer & SS reuse
    }

    // Epilogue: normalize by l and store
    #pragma unroll
    for (int rt = 0; rt < 2; rt++) {
        int ra = wm * 32 + rt * 16 + g;
        int rb = ra + 8;
        float ia = 1.0f / lrow[ra];
        float ib = 1.0f / lrow[rb];
        #pragma unroll
        for (int n = 0; n < 4; n++) {
            int col = wn * 32 + n * 8 + 2 * t;
            *(float2*)&out[((size_t)b * TT + q0 + ra) * HD + col] =
                make_float2(acc[rt][n][0] * ia, acc[rt][n][1] * ia);
            *(float2*)&out[((size_t)b * TT + q0 + rb) * HD + col] =
                make_float2(acc[rt][n][2] * ib, acc[rt][n][3] * ib);
        }
    }
}

// ---------------------------------------------------------------------------
extern "C" void kernel_launch(void* const* d_in, const int* in_sizes, int n_in,
                              void* d_out, int out_size) {
    const float* x      = (const float*)d_in[0];  // [8,2048,1024]
    const float* c_emb  = (const float*)d_in[1];  // [64,64]
    const float* Wq     = (const float*)d_in[2];  // [1024,64]
    const float* Wk     = (const float*)d_in[3];
    const float* Wv     = (const float*)d_in[4];
    const float* gamma  = (const float*)d_in[5];  // [64]
    const float* beta   = (const float*)d_in[6];  // [64]
    float* out          = (float*)d_out;          // [8,2048,64]

    (void)in_sizes; (void)n_in; (void)out_size;

    cudaFuncSetAttribute(attn_kernel,
                         cudaFuncAttributeMaxDynamicSharedMemorySize,
                         ATTN_SMEM_BYTES);

    ln_kernel<<<MM, 64>>>(c_emb, gamma, beta);
    qkv_kernel<<<BT / 64, 256>>>(x, Wq, Wk, Wv);
    dim3 agrid(TT / 128, BB);
    attn_kernel<<<agrid, 256, ATTN_SMEM_BYTES>>>(out);
}

// round 7
// speedup vs baseline: 2.5264x; 1.0882x over previous
#include <cuda_runtime.h>
#include <math.h>

// Problem dims (fixed by reference)
#define BB 8
#define TT 2048
#define DD 1024
#define HD 64
#define MM 64
#define SSZ (TT + MM)          // 2112 keys/values per batch
#define BT (BB * TT)           // 16384 query rows total

// d^-0.5 * log2(e): logits produced directly in log2 domain
#define SCALE_Q 0.18033688011112042f

// Scratch (allocation-free rule: __device__ globals)
// All three hold tf32-rounded values (exact in fp32).
__device__ float g_q[BT * HD];          // prescaled by d^-0.5*log2e
__device__ float g_k[BB * SSZ * HD];
__device__ float g_v[BB * SSZ * HD];

// ---------------------------------------------------------------------------
// Helpers
// ---------------------------------------------------------------------------
__device__ __forceinline__ unsigned tf32u(float x) {
    unsigned u;
    asm("cvt.rna.tf32.f32 %0, %1;" : "=r"(u) : "f"(x));
    return u;
}
__device__ __forceinline__ float tf32r(float x) {
    return __uint_as_float(tf32u(x));
}
__device__ __forceinline__ void mma8(float* c,
                                     unsigned a0, unsigned a1, unsigned a2, unsigned a3,
                                     unsigned b0, unsigned b1) {
    asm volatile(
        "mma.sync.aligned.m16n8k8.row.col.f32.tf32.tf32.f32 "
        "{%0,%1,%2,%3},{%4,%5,%6,%7},{%8,%9},{%0,%1,%2,%3};"
        : "+f"(c[0]), "+f"(c[1]), "+f"(c[2]), "+f"(c[3])
        : "r"(a0), "r"(a1), "r"(a2), "r"(a3), "r"(b0), "r"(b1));
}

// 2^y for y <= 0, FMA-pipe only (no MUFU). |rel err| ~1e-7.
__device__ __forceinline__ float exp2_poly(float y) {
    y = fmaxf(y, -120.0f);
    float fl = floorf(y);
    float f = y - fl;
    float p = 0.0018775767f;
    p = fmaf(p, f, 0.0089893397f);
    p = fmaf(p, f, 0.055826318f);
    p = fmaf(p, f, 0.24015361f);
    p = fmaf(p, f, 0.69315308f);
    p = fmaf(p, f, 0.99999994f);
    float s = __int_as_float(((int)fl + 127) << 23);
    return p * s;
}

__device__ __forceinline__ void cp16(void* smem_dst, const void* gmem_src) {
    unsigned s = (unsigned)__cvta_generic_to_shared(smem_dst);
    asm volatile("cp.async.cg.shared.global [%0], [%1], 16;"
                 :: "r"(s), "l"(gmem_src));
}
#define CP_COMMIT() asm volatile("cp.async.commit_group;" ::: "memory")
#define CP_WAIT0()  asm volatile("cp.async.wait_group 0;" ::: "memory")

// ---------------------------------------------------------------------------
// Kernel 1: layernorm(c_emb) -> broadcast (tf32-rounded) into g_k/g_v tails
// ---------------------------------------------------------------------------
__global__ void ln_kernel(const float* __restrict__ c_emb,
                          const float* __restrict__ gamma,
                          const float* __restrict__ beta) {
    int m = blockIdx.x;
    int t = threadIdx.x;
    __shared__ float red[64];

    float v = c_emb[m * HD + t];
    red[t] = v;
    __syncthreads();
    for (int off = 32; off > 0; off >>= 1) {
        if (t < off) red[t] += red[t + off];
        __syncthreads();
    }
    float mu = red[0] * (1.0f / HD);
    __syncthreads();
    float dv = v - mu;
    red[t] = dv * dv;
    __syncthreads();
    for (int off = 32; off > 0; off >>= 1) {
        if (t < off) red[t] += red[t + off];
        __syncthreads();
    }
    float var = red[0] * (1.0f / HD);
    float y = tf32r(dv * rsqrtf(var + 1e-5f) * gamma[t] + beta[t]);

    #pragma unroll
    for (int b = 0; b < BB; b++) {
        int idx = ((b * SSZ) + TT + m) * HD + t;
        g_k[idx] = y;
        g_v[idx] = y;
    }
}

// ---------------------------------------------------------------------------
// Kernel 2: fused QKV projection via tf32 mma, with register prefetch of the
// next K-chunk (gmem loads overlap mma compute). Math identical to R6.
// ---------------------------------------------------------------------------
#define XS_ST 36
#define WS_ST 196
__global__ __launch_bounds__(256) void qkv_kernel(
    const float* __restrict__ x,
    const float* __restrict__ Wq,
    const float* __restrict__ Wk,
    const float* __restrict__ Wv) {

    __shared__ float xs[64][XS_ST];
    __shared__ float ws[32][WS_ST];

    int tid = threadIdx.x;
    int lane = tid & 31;
    int wid = tid >> 5;
    int wm = wid & 3;
    int wn = wid >> 2;
    int g = lane >> 2;
    int t = lane & 3;
    int row0 = blockIdx.x * 64;

    float acc[12][4];
    #pragma unroll
    for (int n = 0; n < 12; n++)
        #pragma unroll
        for (int i = 0; i < 4; i++) acc[n][i] = 0.0f;

    // Prefetch registers for one 32-wide K-chunk
    float4 xr[2], wqr[2], wkr[2], wvr[2];

    // Load chunk k0 = 0
    #pragma unroll
    for (int i = 0; i < 2; i++) {
        int idx = tid + i * 256;
        int r = idx >> 3;
        int q = idx & 7;
        xr[i] = *(const float4*)&x[(size_t)(row0 + r) * DD + q * 4];
    }
    #pragma unroll
    for (int i = 0; i < 2; i++) {
        int idx = tid + i * 256;
        int r = idx >> 4;
        int q = idx & 15;
        wqr[i] = *(const float4*)&Wq[(size_t)r * HD + q * 4];
        wkr[i] = *(const float4*)&Wk[(size_t)r * HD + q * 4];
        wvr[i] = *(const float4*)&Wv[(size_t)r * HD + q * 4];
    }

    for (int k0 = 0; k0 < DD; k0 += 32) {
        // Store current chunk to smem (tf32-rounded)
        #pragma unroll
        for (int i = 0; i < 2; i++) {
            int idx = tid + i * 256;
            int r = idx >> 3;
            int q = idx & 7;
            xs[r][q * 4 + 0] = tf32r(xr[i].x);
            xs[r][q * 4 + 1] = tf32r(xr[i].y);
            xs[r][q * 4 + 2] = tf32r(xr[i].z);
            xs[r][q * 4 + 3] = tf32r(xr[i].w);
        }
        #pragma unroll
        for (int i = 0; i < 2; i++) {
            int idx = tid + i * 256;
            int r = idx >> 4;
            int q = idx & 15;
            int c = q * 4;
            ws[r][c + 0] = tf32r(wqr[i].x); ws[r][c + 1] = tf32r(wqr[i].y);
            ws[r][c + 2] = tf32r(wqr[i].z); ws[r][c + 3] = tf32r(wqr[i].w);
            ws[r][64 + c + 0] = tf32r(wkr[i].x); ws[r][64 + c + 1] = tf32r(wkr[i].y);
            ws[r][64 + c + 2] = tf32r(wkr[i].z); ws[r][64 + c + 3] = tf32r(wkr[i].w);
            ws[r][128 + c + 0] = tf32r(wvr[i].x); ws[r][128 + c + 1] = tf32r(wvr[i].y);
            ws[r][128 + c + 2] = tf32r(wvr[i].z); ws[r][128 + c + 3] = tf32r(wvr[i].w);
        }
        __syncthreads();

        // Prefetch next chunk (overlaps with mma below)
        if (k0 + 32 < DD) {
            int kn = k0 + 32;
            #pragma unroll
            for (int i = 0; i < 2; i++) {
                int idx = tid + i * 256;
                int r = idx >> 3;
                int q = idx & 7;
                xr[i] = *(const float4*)&x[(size_t)(row0 + r) * DD + kn + q * 4];
            }
            #pragma unroll
            for (int i = 0; i < 2; i++) {
                int idx = tid + i * 256;
                int r = idx >> 4;
                int q = idx & 15;
                wqr[i] = *(const float4*)&Wq[(size_t)(kn + r) * HD + q * 4];
                wkr[i] = *(const float4*)&Wk[(size_t)(kn + r) * HD + q * 4];
                wvr[i] = *(const float4*)&Wv[(size_t)(kn + r) * HD + q * 4];
            }
        }

        #pragma unroll
        for (int kk = 0; kk < 4; kk++) {
            int kb = kk * 8;
            unsigned a0 = __float_as_uint(xs[wm * 16 + g][kb + t]);
            unsigned a1 = __float_as_uint(xs[wm * 16 + g + 8][kb + t]);
            unsigned a2 = __float_as_uint(xs[wm * 16 + g][kb + t + 4]);
            unsigned a3 = __float_as_uint(xs[wm * 16 + g + 8][kb + t + 4]);
            #pragma unroll
            for (int n = 0; n < 12; n++) {
                int nc = wn * 96 + n * 8;
                unsigned b0 = __float_as_uint(ws[kb + t][nc + g]);
                unsigned b1 = __float_as_uint(ws[kb + t + 4][nc + g]);
                mma8(acc[n], a0, a1, a2, a3, b0, b1);
            }
        }
        __syncthreads();
    }

    int r0 = row0 + wm * 16 + g;
    #pragma unroll
    for (int n = 0; n < 12; n++) {
        int nc = wn * 96 + n * 8;
        int mat = nc >> 6;
        int lc = (nc & 63) + 2 * t;
        #pragma unroll
        for (int h = 0; h < 2; h++) {
            int r = r0 + h * 8;
            float v0 = acc[n][h * 2 + 0];
            float v1 = acc[n][h * 2 + 1];
            if (mat == 0) {
                float2 o = make_float2(tf32r(v0 * SCALE_Q), tf32r(v1 * SCALE_Q));
                *(float2*)&g_q[(size_t)r * HD + lc] = o;
            } else {
                int b = r >> 11;
                int rr = r & 2047;
                float2 o = make_float2(tf32r(v0), tf32r(v1));
                if (mat == 1) *(float2*)&g_k[((size_t)b * SSZ + rr) * HD + lc] = o;
                else          *(float2*)&g_v[((size_t)b * SSZ + rr) * HD + lc] = o;
            }
        }
    }
}

// ---------------------------------------------------------------------------
// Kernel 3: flash attention, 128 queries/CTA, warp-private rows.
// 8 warps; warp w owns rows w*16..w*16+15 across the FULL 64 key-columns:
//   - S lives in registers (sc[8][4]); softmax is register + shfl only.
//   - P stashed to a warp-private smem slice (aliased over the Q staging
//     buffer) for phase-C A-fragments; guarded by __syncwarp only.
//   - Q fragments hoisted to registers once.
// One __syncthreads per iteration (K/V double-buffer guard).
// ---------------------------------------------------------------------------
#define TP2 68                               // stride = 4 (mod 32)
#define KVB (64 * TP2)                       // one K or V buffer (floats)
#define ATTN_SMEM_FLOATS (128 * TP2 + 4 * KVB)
#define ATTN_SMEM_BYTES  (ATTN_SMEM_FLOATS * 4)

__global__ __launch_bounds__(256, 1) void attn_kernel(float* __restrict__ out) {
    extern __shared__ float sm[];
    float* ps = sm;                          // [128][TP2]: Q staging, then P
    float* ks = sm + 128 * TP2;              // 2 x [64][TP2]
    float* vs = ks + 2 * KVB;                // 2 x [64][TP2]

    int tid = threadIdx.x;
    int lane = tid & 31;
    int w = tid >> 5;                        // warp id: rows w*16..w*16+15
    int g = lane >> 2;
    int t = lane & 3;
    int b = blockIdx.y;
    int q0 = blockIdx.x * 128;
    int r0 = w * 16;

    // Stage Q 128x64 (coalesced), then hoist this warp's fragments to regs
    #pragma unroll
    for (int i = 0; i < 8; i++) {
        int idx = tid + i * 256;
        int r = idx >> 4;
        int q = idx & 15;
        float4 v = *(const float4*)&g_q[((size_t)b * TT + q0 + r) * HD + q * 4];
        *(float4*)&ps[r * TP2 + q * 4] = v;
    }
    __syncthreads();
    unsigned qf[8][4];
    #pragma unroll
    for (int kk = 0; kk < 8; kk++) {
        int kb = kk * 8;
        qf[kk][0] = __float_as_uint(ps[(r0 + g) * TP2 + kb + t]);
        qf[kk][1] = __float_as_uint(ps[(r0 + g + 8) * TP2 + kb + t]);
        qf[kk][2] = __float_as_uint(ps[(r0 + g) * TP2 + kb + t + 4]);
        qf[kk][3] = __float_as_uint(ps[(r0 + g + 8) * TP2 + kb + t + 4]);
    }
    // ps rows r0..r0+15 are warp-private from here on (reused for P)

    // Prologue: async-load K/V tile 0 into buffer 0
    #pragma unroll
    for (int it = 0; it < 4; it++) {
        int idx = tid + it * 256;
        int r = idx >> 4;
        int q = idx & 15;
        size_t src = ((size_t)b * SSZ + r) * HD + q * 4;
        cp16(ks + r * TP2 + q * 4, &g_k[src]);
        cp16(vs + r * TP2 + q * 4, &g_v[src]);
    }
    CP_COMMIT();

    float m0 = -1e30f, m1 = -1e30f, l0 = 0.0f, l1 = 0.0f;
    float acc[8][4];
    #pragma unroll
    for (int n = 0; n < 8; n++)
        #pragma unroll
        for (int i = 0; i < 4; i++) acc[n][i] = 0.0f;

    for (int ti = 0; ti < 33; ti++) {
        CP_WAIT0();
        __syncthreads();   // tile ti visible; everyone done with prev iter

        // Kick off next tile into the other buffer (overlaps with compute)
        if (ti < 32) {
            int s0 = (ti + 1) * 64;
            float* kb_ = ks + ((ti + 1) & 1) * KVB;
            float* vb_ = vs + ((ti + 1) & 1) * KVB;
            #pragma unroll
            for (int it = 0; it < 4; it++) {
                int idx = tid + it * 256;
                int r = idx >> 4;
                int q = idx & 15;
                size_t src = ((size_t)b * SSZ + s0 + r) * HD + q * 4;
                cp16(kb_ + r * TP2 + q * 4, &g_k[src]);
                cp16(vb_ + r * TP2 + q * 4, &g_v[src]);
            }
            CP_COMMIT();
        }

        const float* kcur = ks + (ti & 1) * KVB;
        const float* vcur = vs + (ti & 1) * KVB;

        // Phase A: S = Q * K^T  (warp 16 rows x 64 cols, Q frags in regs)
        float sc[8][4];
        #pragma unroll
        for (int n = 0; n < 8; n++)
            #pragma unroll
            for (int i = 0; i < 4; i++) sc[n][i] = 0.0f;
        #pragma unroll
        for (int kk = 0; kk < 8; kk++) {
            int kb = kk * 8;
            #pragma unroll
            for (int n = 0; n < 8; n++) {
                unsigned b0 = __float_as_uint(kcur[(n * 8 + g) * TP2 + kb + t]);
                unsigned b1 = __float_as_uint(kcur[(n * 8 + g) * TP2 + kb + t + 4]);
                mma8(sc[n], qf[kk][0], qf[kk][1], qf[kk][2], qf[kk][3], b0, b1);
            }
        }

        // Softmax: fully in registers. Row r0+g -> sc[n][0..1], row r0+g+8 -> sc[n][2..3].
        float mx0 = -1e30f, mx1 = -1e30f;
        #pragma unroll
        for (int n = 0; n < 8; n++) {
            mx0 = fmaxf(mx0, fmaxf(sc[n][0], sc[n][1]));
            mx1 = fmaxf(mx1, fmaxf(sc[n][2], sc[n][3]));
        }
        mx0 = fmaxf(mx0, __shfl_xor_sync(0xffffffffu, mx0, 1));
        mx0 = fmaxf(mx0, __shfl_xor_sync(0xffffffffu, mx0, 2));
        mx1 = fmaxf(mx1, __shfl_xor_sync(0xffffffffu, mx1, 1));
        mx1 = fmaxf(mx1, __shfl_xor_sync(0xffffffffu, mx1, 2));
        float mn0 = fmaxf(m0, mx0);
        float mn1 = fmaxf(m1, mx1);
        float f0 = exp2_poly(m0 - mn0);
        float f1 = exp2_poly(m1 - mn1);
        float s0 = 0.0f, s1 = 0.0f;
        #pragma unroll
        for (int n = 0; n < 8; n++) {
            sc[n][0] = tf32r(exp2_poly(sc[n][0] - mn0)); s0 += sc[n][0];
            sc[n][1] = tf32r(exp2_poly(sc[n][1] - mn0)); s0 += sc[n][1];
            sc[n][2] = tf32r(exp2_poly(sc[n][2] - mn1)); s1 += sc[n][2];
            sc[n][3] = tf32r(exp2_poly(sc[n][3] - mn1)); s1 += sc[n][3];
        }
        s0 += __shfl_xor_sync(0xffffffffu, s0, 1);
        s0 += __shfl_xor_sync(0xffffffffu, s0, 2);
        s1 += __shfl_xor_sync(0xffffffffu, s1, 1);
        s1 += __shfl_xor_sync(0xffffffffu, s1, 2);
        l0 = l0 * f0 + s0;
        l1 = l1 * f1 + s1;
        m0 = mn0;
        m1 = mn1;
        #pragma unroll
        for (int n = 0; n < 8; n++) {
            acc[n][0] *= f0; acc[n][1] *= f0;
            acc[n][2] *= f1; acc[n][3] *= f1;
        }

        // Stash P into warp-private slice for phase-C A-fragment layout
        #pragma unroll
        for (int n = 0; n < 8; n++) {
            *(float2*)&ps[(r0 + g) * TP2 + n * 8 + 2 * t] =
                make_float2(sc[n][0], sc[n][1]);
            *(float2*)&ps[(r0 + g + 8) * TP2 + n * 8 + 2 * t] =
                make_float2(sc[n][2], sc[n][3]);
        }
        __syncwarp();

        // Phase C: O += P * V  (warp 16 rows x 64 cols)
        #pragma unroll
        for (int kk = 0; kk < 8; kk++) {
            int kb = kk * 8;
            unsigned a0 = __float_as_uint(ps[(r0 + g) * TP2 + kb + t]);
            unsigned a1 = __float_as_uint(ps[(r0 + g + 8) * TP2 + kb + t]);
            unsigned a2 = __float_as_uint(ps[(r0 + g) * TP2 + kb + t + 4]);
            unsigned a3 = __float_as_uint(ps[(r0 + g + 8) * TP2 + kb + t + 4]);
            #pragma unroll
            for (int n = 0; n < 8; n++) {
                unsigned b0 = __float_as_uint(vcur[(kb + t) * TP2 + n * 8 + g]);
                unsigned b1 = __float_as_uint(vcur[(kb + t + 4) * TP2 + n * 8 + g]);
                mma8(acc[n], a0, a1, a2, a3, b0, b1);
            }
        }
        // next-iter __syncthreads guards K/V buffer and P-slice reuse
    }

    // Epilogue: normalize by l and store
    float ia = 1.0f / l0;
    float ib = 1.0f / l1;
    int ra = q0 + r0 + g;
    int rb = ra + 8;
    #pragma unroll
    for (int n = 0; n < 8; n++) {
        int col = n * 8 + 2 * t;
        *(float2*)&out[((size_t)b * TT + ra) * HD + col] =
            make_float2(acc[n][0] * ia, acc[n][1] * ia);
        *(float2*)&out[((size_t)b * TT + rb) * HD + col] =
            make_float2(acc[n][2] * ib, acc[n][3] * ib);
    }
}

// ---------------------------------------------------------------------------
extern "C" void kernel_launch(void* const* d_in, const int* in_sizes, int n_in,
                              void* d_out, int out_size) {
    const float* x      = (const float*)d_in[0];  // [8,2048,1024]
    const float* c_emb  = (const float*)d_in[1];  // [64,64]
    const float* Wq     = (const float*)d_in[2];  // [1024,64]
    const float* Wk     = (const float*)d_in[3];
    const float* Wv     = (const float*)d_in[4];
    const float* gamma  = (const float*)d_in[5];  // [64]
    const float* beta   = (const float*)d_in[6];  // [64]
    float* out          = (float*)d_out;          // [8,2048,64]

    (void)in_sizes; (void)n_in; (void)out_size;

    cudaFuncSetAttribute(attn_kernel,
                         cudaFuncAttributeMaxDynamicSharedMemorySize,
                         ATTN_SMEM_BYTES);

    ln_kernel<<<MM, 64>>>(c_emb, gamma, beta);
    qkv_kernel<<<BT / 64, 256>>>(x, Wq, Wk, Wv);
    dim3 agrid(TT / 128, BB);
    attn_kernel<<<agrid, 256, ATTN_SMEM_BYTES>>>(out);
}

// round 10
// speedup vs baseline: 2.9489x; 1.1672x over previous
#include <cuda_runtime.h>
#include <math.h>

// Problem dims (fixed by reference)
#define BB 8
#define TT 2048
#define DD 1024
#define HD 64
#define MM 64
#define SSZ (TT + MM)          // 2112 keys/values per batch
#define BT (BB * TT)           // 16384 query rows total

// d^-0.5 * log2(e): logits produced directly in log2 domain
#define SCALE_Q 0.18033688011112042f

// Scratch (allocation-free rule: __device__ globals)
__device__ float g_q[BT * HD];          // prescaled by d^-0.5*log2e
__device__ float g_k[BB * SSZ * HD];
__device__ float g_v[BB * SSZ * HD];

// ---------------------------------------------------------------------------
// Helpers
// ---------------------------------------------------------------------------
__device__ __forceinline__ unsigned tf32u(float x) {
    unsigned u;
    asm("cvt.rna.tf32.f32 %0, %1;" : "=r"(u) : "f"(x));
    return u;
}
__device__ __forceinline__ float tf32r(float x) {
    return __uint_as_float(tf32u(x));
}
__device__ __forceinline__ void mma8(float* c,
                                     unsigned a0, unsigned a1, unsigned a2, unsigned a3,
                                     unsigned b0, unsigned b1) {
    asm volatile(
        "mma.sync.aligned.m16n8k8.row.col.f32.tf32.tf32.f32 "
        "{%0,%1,%2,%3},{%4,%5,%6,%7},{%8,%9},{%0,%1,%2,%3};"
        : "+f"(c[0]), "+f"(c[1]), "+f"(c[2]), "+f"(c[3])
        : "r"(a0), "r"(a1), "r"(a2), "r"(a3), "r"(b0), "r"(b1));
}

// 2^y via MUFU (single instruction, separate pipe). rel err ~1e-6.
__device__ __forceinline__ float exp2a(float y) {
    float r;
    asm("ex2.approx.f32 %0, %1;" : "=f"(r) : "f"(y));
    return r;
}

__device__ __forceinline__ void cp16(void* smem_dst, const void* gmem_src) {
    unsigned s = (unsigned)__cvta_generic_to_shared(smem_dst);
    asm volatile("cp.async.cg.shared.global [%0], [%1], 16;"
                 :: "r"(s), "l"(gmem_src));
}
#define CP_COMMIT() asm volatile("cp.async.commit_group;" ::: "memory")
#define CP_WAIT0()  asm volatile("cp.async.wait_group 0;" ::: "memory")

// ---------------------------------------------------------------------------
// Kernel 1: layernorm(c_emb) -> broadcast (tf32-rounded) into g_k/g_v tails
// ---------------------------------------------------------------------------
__global__ void ln_kernel(const float* __restrict__ c_emb,
                          const float* __restrict__ gamma,
                          const float* __restrict__ beta) {
    int m = blockIdx.x;
    int t = threadIdx.x;
    __shared__ float red[64];

    float v = c_emb[m * HD + t];
    red[t] = v;
    __syncthreads();
    for (int off = 32; off > 0; off >>= 1) {
        if (t < off) red[t] += red[t + off];
        __syncthreads();
    }
    float mu = red[0] * (1.0f / HD);
    __syncthreads();
    float dv = v - mu;
    red[t] = dv * dv;
    __syncthreads();
    for (int off = 32; off > 0; off >>= 1) {
        if (t < off) red[t] += red[t + off];
        __syncthreads();
    }
    float var = red[0] * (1.0f / HD);
    float y = tf32r(dv * rsqrtf(var + 1e-5f) * gamma[t] + beta[t]);

    #pragma unroll
    for (int b = 0; b < BB; b++) {
        int idx = ((b * SSZ) + TT + m) * HD + t;
        g_k[idx] = y;
        g_v[idx] = y;
    }
}

// ---------------------------------------------------------------------------
// Kernel 2: fused QKV projection via tf32 mma + register prefetch (as R7).
// ---------------------------------------------------------------------------
#define XS_ST 36
#define WS_ST 196
__global__ __launch_bounds__(256) void qkv_kernel(
    const float* __restrict__ x,
    const float* __restrict__ Wq,
    const float* __restrict__ Wk,
    const float* __restrict__ Wv) {

    __shared__ float xs[64][XS_ST];
    __shared__ float ws[32][WS_ST];

    int tid = threadIdx.x;
    int lane = tid & 31;
    int wid = tid >> 5;
    int wm = wid & 3;
    int wn = wid >> 2;
    int g = lane >> 2;
    int t = lane & 3;
    int row0 = blockIdx.x * 64;

    float acc[12][4];
    #pragma unroll
    for (int n = 0; n < 12; n++)
        #pragma unroll
        for (int i = 0; i < 4; i++) acc[n][i] = 0.0f;

    float4 xr[2], wqr[2], wkr[2], wvr[2];

    #pragma unroll
    for (int i = 0; i < 2; i++) {
        int idx = tid + i * 256;
        int r = idx >> 3;
        int q = idx & 7;
        xr[i] = *(const float4*)&x[(size_t)(row0 + r) * DD + q * 4];
    }
    #pragma unroll
    for (int i = 0; i < 2; i++) {
        int idx = tid + i * 256;
        int r = idx >> 4;
        int q = idx & 15;
        wqr[i] = *(const float4*)&Wq[(size_t)r * HD + q * 4];
        wkr[i] = *(const float4*)&Wk[(size_t)r * HD + q * 4];
        wvr[i] = *(const float4*)&Wv[(size_t)r * HD + q * 4];
    }

    for (int k0 = 0; k0 < DD; k0 += 32) {
        #pragma unroll
        for (int i = 0; i < 2; i++) {
            int idx = tid + i * 256;
            int r = idx >> 3;
            int q = idx & 7;
            xs[r][q * 4 + 0] = tf32r(xr[i].x);
            xs[r][q * 4 + 1] = tf32r(xr[i].y);
            xs[r][q * 4 + 2] = tf32r(xr[i].z);
            xs[r][q * 4 + 3] = tf32r(xr[i].w);
        }
        #pragma unroll
        for (int i = 0; i < 2; i++) {
            int idx = tid + i * 256;
            int r = idx >> 4;
            int q = idx & 15;
            int c = q * 4;
            ws[r][c + 0] = tf32r(wqr[i].x); ws[r][c + 1] = tf32r(wqr[i].y);
            ws[r][c + 2] = tf32r(wqr[i].z); ws[r][c + 3] = tf32r(wqr[i].w);
            ws[r][64 + c + 0] = tf32r(wkr[i].x); ws[r][64 + c + 1] = tf32r(wkr[i].y);
            ws[r][64 + c + 2] = tf32r(wkr[i].z); ws[r][64 + c + 3] = tf32r(wkr[i].w);
            ws[r][128 + c + 0] = tf32r(wvr[i].x); ws[r][128 + c + 1] = tf32r(wvr[i].y);
            ws[r][128 + c + 2] = tf32r(wvr[i].z); ws[r][128 + c + 3] = tf32r(wvr[i].w);
        }
        __syncthreads();

        if (k0 + 32 < DD) {
            int kn = k0 + 32;
            #pragma unroll
            for (int i = 0; i < 2; i++) {
                int idx = tid + i * 256;
                int r = idx >> 3;
                int q = idx & 7;
                xr[i] = *(const float4*)&x[(size_t)(row0 + r) * DD + kn + q * 4];
            }
            #pragma unroll
            for (int i = 0; i < 2; i++) {
                int idx = tid + i * 256;
                int r = idx >> 4;
                int q = idx & 15;
                wqr[i] = *(const float4*)&Wq[(size_t)(kn + r) * HD + q * 4];
                wkr[i] = *(const float4*)&Wk[(size_t)(kn + r) * HD + q * 4];
                wvr[i] = *(const float4*)&Wv[(size_t)(kn + r) * HD + q * 4];
            }
        }

        #pragma unroll
        for (int kk = 0; kk < 4; kk++) {
            int kb = kk * 8;
            unsigned a0 = __float_as_uint(xs[wm * 16 + g][kb + t]);
            unsigned a1 = __float_as_uint(xs[wm * 16 + g + 8][kb + t]);
            unsigned a2 = __float_as_uint(xs[wm * 16 + g][kb + t + 4]);
            unsigned a3 = __float_as_uint(xs[wm * 16 + g + 8][kb + t + 4]);
            #pragma unroll
            for (int n = 0; n < 12; n++) {
                int nc = wn * 96 + n * 8;
                unsigned b0 = __float_as_uint(ws[kb + t][nc + g]);
                unsigned b1 = __float_as_uint(ws[kb + t + 4][nc + g]);
                mma8(acc[n], a0, a1, a2, a3, b0, b1);
            }
        }
        __syncthreads();
    }

    int r0 = row0 + wm * 16 + g;
    #pragma unroll
    for (int n = 0; n < 12; n++) {
        int nc = wn * 96 + n * 8;
        int mat = nc >> 6;
        int lc = (nc & 63) + 2 * t;
        #pragma unroll
        for (int h = 0; h < 2; h++) {
            int r = r0 + h * 8;
            float v0 = acc[n][h * 2 + 0];
            float v1 = acc[n][h * 2 + 1];
            if (mat == 0) {
                float2 o = make_float2(tf32r(v0 * SCALE_Q), tf32r(v1 * SCALE_Q));
                *(float2*)&g_q[(size_t)r * HD + lc] = o;
            } else {
                int b = r >> 11;
                int rr = r & 2047;
                float2 o = make_float2(tf32r(v0), tf32r(v1));
                if (mat == 1) *(float2*)&g_k[((size_t)b * SSZ + rr) * HD + lc] = o;
                else          *(float2*)&g_v[((size_t)b * SSZ + rr) * HD + lc] = o;
            }
        }
    }
}

// ---------------------------------------------------------------------------
// Kernel 3: flash attention v3. 128 queries/CTA, 4 warps x 32 rows each.
// Doubled B-fragment reuse (each K/V smem byte feeds 32 rows, not 16) cuts
// smem crossbar traffic ~40%. Softmax exp on MUFU (ex2.approx). S stays in
// registers; P stashed to warp-private smem rows; 1 __syncthreads per tile.
// ---------------------------------------------------------------------------
#define TP2 68                               // stride = 4 (mod 32)
#define KVB (64 * TP2)                       // one K or V buffer (floats)
#define ATTN_SMEM_FLOATS (2 * 128 * TP2 + 4 * KVB)
#define ATTN_SMEM_BYTES  (ATTN_SMEM_FLOATS * 4)

__global__ __launch_bounds__(128, 1) void attn_kernel(float* __restrict__ out) {
    extern __shared__ float sm[];
    float* qs = sm;                          // [128][TP2] Q (persistent)
    float* ps = sm + 128 * TP2;              // [128][TP2] P (warp-private rows)
    float* ks = sm + 2 * 128 * TP2;          // 2 x [64][TP2]
    float* vs = ks + 2 * KVB;                // 2 x [64][TP2]

    int tid = threadIdx.x;
    int lane = tid & 31;
    int w = tid >> 5;                        // warp id: rows w*32..w*32+31
    int g = lane >> 2;
    int t = lane & 3;
    int b = blockIdx.y;
    int q0 = blockIdx.x * 128;
    int r0 = w * 32;

    // Stage Q 128x64 (coalesced)
    #pragma unroll
    for (int i = 0; i < 16; i++) {
        int idx = tid + i * 128;
        int r = idx >> 4;
        int q = idx & 15;
        float4 v = *(const float4*)&g_q[((size_t)b * TT + q0 + r) * HD + q * 4];
        *(float4*)&qs[r * TP2 + q * 4] = v;
    }

    // Prologue: async-load K/V tile 0 into buffer 0
    #pragma unroll
    for (int it = 0; it < 8; it++) {
        int idx = tid + it * 128;
        int r = idx >> 4;
        int q = idx & 15;
        size_t src = ((size_t)b * SSZ + r) * HD + q * 4;
        cp16(ks + r * TP2 + q * 4, &g_k[src]);
        cp16(vs + r * TP2 + q * 4, &g_v[src]);
    }
    CP_COMMIT();

    // Row stats: h=0 -> rows r0+g, r0+g+8; h=1 -> rows r0+16+g, r0+16+g+8
    float m[4] = {-1e30f, -1e30f, -1e30f, -1e30f};
    float l[4] = {0.0f, 0.0f, 0.0f, 0.0f};
    float acc[2][8][4];
    #pragma unroll
    for (int h = 0; h < 2; h++)
        #pragma unroll
        for (int n = 0; n < 8; n++)
            #pragma unroll
            for (int i = 0; i < 4; i++) acc[h][n][i] = 0.0f;

    for (int ti = 0; ti < 33; ti++) {
        CP_WAIT0();
        __syncthreads();   // tile ti visible; everyone done with prev iter

        if (ti < 32) {
            int s0 = (ti + 1) * 64;
            float* kb_ = ks + ((ti + 1) & 1) * KVB;
            float* vb_ = vs + ((ti + 1) & 1) * KVB;
            #pragma unroll
            for (int it = 0; it < 8; it++) {
                int idx = tid + it * 128;
                int r = idx >> 4;
                int q = idx & 15;
                size_t src = ((size_t)b * SSZ + s0 + r) * HD + q * 4;
                cp16(kb_ + r * TP2 + q * 4, &g_k[src]);
                cp16(vb_ + r * TP2 + q * 4, &g_v[src]);
            }
            CP_COMMIT();
        }

        const float* kcur = ks + (ti & 1) * KVB;
        const float* vcur = vs + (ti & 1) * KVB;

        // Phase A: S = Q * K^T  (warp: 32 rows x 64 cols; K frags reused 2x)
        float sc[2][8][4];
        #pragma unroll
        for (int h = 0; h < 2; h++)
            #pragma unroll
            for (int n = 0; n < 8; n++)
                #pragma unroll
                for (int i = 0; i < 4; i++) sc[h][n][i] = 0.0f;
        #pragma unroll
        for (int kk = 0; kk < 8; kk++) {
            int kb = kk * 8;
            unsigned a[2][4];
            #pragma unroll
            for (int h = 0; h < 2; h++) {
                int rr = r0 + h * 16 + g;
                a[h][0] = __float_as_uint(qs[rr * TP2 + kb + t]);
                a[h][1] = __float_as_uint(qs[(rr + 8) * TP2 + kb + t]);
                a[h][2] = __float_as_uint(qs[rr * TP2 + kb + t + 4]);
                a[h][3] = __float_as_uint(qs[(rr + 8) * TP2 + kb + t + 4]);
            }
            #pragma unroll
            for (int n = 0; n < 8; n++) {
                unsigned b0 = __float_as_uint(kcur[(n * 8 + g) * TP2 + kb + t]);
                unsigned b1 = __float_as_uint(kcur[(n * 8 + g) * TP2 + kb + t + 4]);
                mma8(sc[0][n], a[0][0], a[0][1], a[0][2], a[0][3], b0, b1);
                mma8(sc[1][n], a[1][0], a[1][1], a[1][2], a[1][3], b0, b1);
            }
        }

        // Softmax (registers + shfl; exp on MUFU), then stash P
        #pragma unroll
        for (int h = 0; h < 2; h++) {
            float mx0 = -1e30f, mx1 = -1e30f;
            #pragma unroll
            for (int n = 0; n < 8; n++) {
                mx0 = fmaxf(mx0, fmaxf(sc[h][n][0], sc[h][n][1]));
                mx1 = fmaxf(mx1, fmaxf(sc[h][n][2], sc[h][n][3]));
            }
            mx0 = fmaxf(mx0, __shfl_xor_sync(0xffffffffu, mx0, 1));
            mx0 = fmaxf(mx0, __shfl_xor_sync(0xffffffffu, mx0, 2));
            mx1 = fmaxf(mx1, __shfl_xor_sync(0xffffffffu, mx1, 1));
            mx1 = fmaxf(mx1, __shfl_xor_sync(0xffffffffu, mx1, 2));
            float mn0 = fmaxf(m[2 * h], mx0);
            float mn1 = fmaxf(m[2 * h + 1], mx1);
            float f0 = exp2a(m[2 * h] - mn0);
            float f1 = exp2a(m[2 * h + 1] - mn1);
            float s0 = 0.0f, s1 = 0.0f;
            #pragma unroll
            for (int n = 0; n < 8; n++) {
                sc[h][n][0] = tf32r(exp2a(sc[h][n][0] - mn0)); s0 += sc[h][n][0];
                sc[h][n][1] = tf32r(exp2a(sc[h][n][1] - mn0)); s0 += sc[h][n][1];
                sc[h][n][2] = tf32r(exp2a(sc[h][n][2] - mn1)); s1 += sc[h][n][2];
                sc[h][n][3] = tf32r(exp2a(sc[h][n][3] - mn1)); s1 += sc[h][n][3];
            }
            s0 += __shfl_xor_sync(0xffffffffu, s0, 1);
            s0 += __shfl_xor_sync(0xffffffffu, s0, 2);
            s1 += __shfl_xor_sync(0xffffffffu, s1, 1);
            s1 += __shfl_xor_sync(0xffffffffu, s1, 2);
            l[2 * h]     = l[2 * h] * f0 + s0;
            l[2 * h + 1] = l[2 * h + 1] * f1 + s1;
            m[2 * h]     = mn0;
            m[2 * h + 1] = mn1;
            #pragma unroll
            for (int n = 0; n < 8; n++) {
                acc[h][n][0] *= f0; acc[h][n][1] *= f0;
                acc[h][n][2] *= f1; acc[h][n][3] *= f1;
            }
            int rr = r0 + h * 16 + g;
            #pragma unroll
            for (int n = 0; n < 8; n++) {
                *(float2*)&ps[rr * TP2 + n * 8 + 2 * t] =
                    make_float2(sc[h][n][0], sc[h][n][1]);
                *(float2*)&ps[(rr + 8) * TP2 + n * 8 + 2 * t] =
                    make_float2(sc[h][n][2], sc[h][n][3]);
            }
        }
        __syncwarp();

        // Phase C: O += P * V  (warp: 32 rows x 64 cols; V frags reused 2x)
        #pragma unroll
        for (int kk = 0; kk < 8; kk++) {
            int kb = kk * 8;
            unsigned a[2][4];
            #pragma unroll
            for (int h = 0; h < 2; h++) {
                int rr = r0 + h * 16 + g;
                a[h][0] = __float_as_uint(ps[rr * TP2 + kb + t]);
                a[h][1] = __float_as_uint(ps[(rr + 8) * TP2 + kb + t]);
                a[h][2] = __float_as_uint(ps[rr * TP2 + kb + t + 4]);
                a[h][3] = __float_as_uint(ps[(rr + 8) * TP2 + kb + t + 4]);
            }
            #pragma unroll
            for (int n = 0; n < 8; n++) {
                unsigned b0 = __float_as_uint(vcur[(kb + t) * TP2 + n * 8 + g]);
                unsigned b1 = __float_as_uint(vcur[(kb + t + 4) * TP2 + n * 8 + g]);
                mma8(acc[0][n], a[0][0], a[0][1], a[0][2], a[0][3], b0, b1);
                mma8(acc[1][n], a[1][0], a[1][1], a[1][2], a[1][3], b0, b1);
            }
        }
        // next-iter __syncthreads guards K/V buffer and P-slice reuse
    }

    // Epilogue: normalize by l and store
    #pragma unroll
    for (int h = 0; h < 2; h++) {
        int ra = q0 + r0 + h * 16 + g;
        int rb = ra + 8;
        float ia = 1.0f / l[2 * h];
        float ib = 1.0f / l[2 * h + 1];
        #pragma unroll
        for (int n = 0; n < 8; n++) {
            int col = n * 8 + 2 * t;
            *(float2*)&out[((size_t)b * TT + ra) * HD + col] =
                make_float2(acc[h][n][0] * ia, acc[h][n][1] * ia);
            *(float2*)&out[((size_t)b * TT + rb) * HD + col] =
                make_float2(acc[h][n][2] * ib, acc[h][n][3] * ib);
        }
    }
}

// ---------------------------------------------------------------------------
extern "C" void kernel_launch(void* const* d_in, const int* in_sizes, int n_in,
                              void* d_out, int out_size) {
    const float* x      = (const float*)d_in[0];  // [8,2048,1024]
    const float* c_emb  = (const float*)d_in[1];  // [64,64]
    const float* Wq     = (const float*)d_in[2];  // [1024,64]
    const float* Wk     = (const float*)d_in[3];
    const float* Wv     = (const float*)d_in[4];
    const float* gamma  = (const float*)d_in[5];  // [64]
    const float* beta   = (const float*)d_in[6];  // [64]
    float* out          = (float*)d_out;          // [8,2048,64]

    (void)in_sizes; (void)n_in; (void)out_size;

    cudaFuncSetAttribute(attn_kernel,
                         cudaFuncAttributeMaxDynamicSharedMemorySize,
                         ATTN_SMEM_BYTES);

    ln_kernel<<<MM, 64>>>(c_emb, gamma, beta);
    qkv_kernel<<<BT / 64, 256>>>(x, Wq, Wk, Wv);
    dim3 agrid(TT / 128, BB);
    attn_kernel<<<agrid, 128, ATTN_SMEM_BYTES>>>(out);
}